// round 15
// baseline (speedup 1.0000x reference)
#include <cuda_runtime.h>
#include <cstdint>

// ---------------- constants ----------------
#define NCAND   1600
#define NBND    (NCAND * 15)        // 24000
#define NB      131072              // fine value bins
#define TPB     256
#define GRID1   592                 // k1 blocks
#define K2G     128                 // k2 blocks (resident -> grid barrier safe)
#define GRID3   888                 // k3 blocks (6/SM)
#define K4G     128                 // k4 blocks (resident)
#define K4T     512                 // k4 threads (2 bins/thread)
#define EPS_F32 1.1920928955078125e-07f
#define FXS     1099511627776.0f    // 2^40
#define FXSI    (1.0 / 1099511627776.0)
#define PMASK   0x0000FFFFFFFFFFFFULL

// ---------------- device state (zero-initialized at module load; every ------
// ---------------- consumer re-zeroes what it finishes with, so replays ------
// ---------------- always start from zeroed scratch) --------------------------
__device__ unsigned g_bminenc[GRID1], g_bmaxenc[GRID1];
__device__ float    g_xminF, g_xmaxF, g_bsF, g_binwF;
__device__ float    g_scale[NCAND], g_zp[NCAND], g_cmin[NCAND], g_cmax[NCAND];
__device__ float    g_bndval[NBND];
__device__ int      g_bndbin[NBND];
__device__ unsigned g_bndcnt[NB];
__device__ unsigned g_bndmeta[NB];      // (csr_off << 16) | cnt
__device__ unsigned g_bndcur[NB];
__device__ uint2    g_list[NBND];       // {valbits, id}
__device__ unsigned g_bitmap[NB / 32];
__device__ __align__(16) unsigned long long g_acc[NB];
__device__ unsigned long long g_part[NBND];
__device__ unsigned g_pwcnt[NB];
__device__ double   g_pwsx[NB];
__device__ unsigned g_psum2[K2G];
__device__ unsigned g_ptotc[K4G];
__device__ double   g_ptotx[K4G];
__device__ double   g_totsx;
__device__ double   g_scores[NCAND];
__device__ unsigned g_bars[8];

// ---------------- helpers ----------------
__device__ __forceinline__ unsigned enc_f32(float f) {
    unsigned u = __float_as_uint(f);
    return (u & 0x80000000u) ? ~u : (u | 0x80000000u);
}
__device__ __forceinline__ float dec_f32(unsigned e) {
    unsigned u = (e & 0x80000000u) ? (e ^ 0x80000000u) : ~e;
    return __uint_as_float(u);
}
__device__ __forceinline__ int binof(float v, float xmin, float bs) {
    int j = (int)((v - xmin) * bs);
    j = j < 0 ? 0 : j;
    return j < NB ? j : (NB - 1);
}
__device__ __forceinline__ float binlo(int j, float xmin, float binw) {
    return __fmaf_rn((float)j, binw, xmin);
}
// software grid barrier — requires all gridDim blocks resident
__device__ __forceinline__ void gbar(unsigned* ctr, unsigned target) {
    __threadfence();
    __syncthreads();
    if (threadIdx.x == 0) {
        atomicAdd(ctr, 1u);
        while (*((volatile unsigned*)ctr) < target) {}
    }
    __syncthreads();
}
__device__ __forceinline__ void cand_params(int c, float x_min, float x_max,
                                            float& scale, float& zp,
                                            float& nmin, float& nmax) {
    float xrange = x_max - x_min;
    int i = c / 16 + 1;
    int j = c % 16;
    float fi = (float)i, zj = (float)j;
    float tmp_max   = __fmul_rn(__fdiv_rn(xrange, 100.0f), fi);
    float tmp_delta = __fdiv_rn(tmp_max, 15.0f);
    float zd = __fmul_rn(zj, tmp_delta);
    nmin = fmaxf(-zd, x_min);
    nmax = fminf(__fsub_rn(tmp_max, zd), x_max);
    float min_neg = fminf(nmin, 0.0f);
    float max_pos = fmaxf(nmax, 0.0f);
    scale = fmaxf(__fdiv_rn(__fsub_rn(max_pos, min_neg), 15.0f), EPS_F32);
    zp = fminf(fmaxf(0.0f - rintf(__fdiv_rn(min_neg, scale)), 0.0f), 15.0f);
}

// ================= k1: global min/max (+ bar reset only) ====================
__global__ void __launch_bounds__(TPB) k1_minmax(const float* __restrict__ x, int n) {
    int tid = blockIdx.x * TPB + threadIdx.x;
    int stride = GRID1 * TPB;
    if (tid < 8) g_bars[tid] = 0u;

    float lmin = 3.4e38f, lmax = -3.4e38f;
    int n4 = n >> 2;
    const float4* x4 = (const float4*)x;
    for (int p = tid; p < n4; p += stride) {
        float4 v = __ldg(x4 + p);
        lmin = fminf(lmin, fminf(fminf(v.x, v.y), fminf(v.z, v.w)));
        lmax = fmaxf(lmax, fmaxf(fmaxf(v.x, v.y), fmaxf(v.z, v.w)));
    }
    int r = n & 3;
    if (tid < r) {
        float v = x[n - r + tid];
        lmin = fminf(lmin, v);
        lmax = fmaxf(lmax, v);
    }
    unsigned emin = __reduce_min_sync(0xFFFFFFFFu, enc_f32(lmin));
    unsigned emax = __reduce_max_sync(0xFFFFFFFFu, enc_f32(lmax));
    __shared__ unsigned smn[TPB / 32], smx[TPB / 32];
    int wid = threadIdx.x >> 5, lane = threadIdx.x & 31;
    if (lane == 0) { smn[wid] = emin; smx[wid] = emax; }
    __syncthreads();
    if (wid == 0) {
        unsigned a = (lane < TPB / 32) ? smn[lane] : 0xFFFFFFFFu;
        unsigned b = (lane < TPB / 32) ? smx[lane] : 0u;
        a = __reduce_min_sync(0xFFFFFFFFu, a);
        b = __reduce_max_sync(0xFFFFFFFFu, b);
        if (lane == 0) { g_bminenc[blockIdx.x] = a; g_bmaxenc[blockIdx.x] = b; }
    }
}

// ================= k2: minmax-reduce + candidates + boundary CSR ============
__global__ void __launch_bounds__(256) k2_bnd() {
    int t = threadIdx.x, b = blockIdx.x;
    int gid = b * 256 + t;

    // phase 0: block 0 reduces per-block minmax partials
    if (b == 0) {
        unsigned emin = 0xFFFFFFFFu, emax = 0u;
        for (int i = t; i < GRID1; i += 256) {
            emin = min(emin, g_bminenc[i]);
            emax = max(emax, g_bmaxenc[i]);
        }
        emin = __reduce_min_sync(0xFFFFFFFFu, emin);
        emax = __reduce_max_sync(0xFFFFFFFFu, emax);
        __shared__ unsigned smn[8], smx[8];
        int wid = t >> 5, lane = t & 31;
        if (lane == 0) { smn[wid] = emin; smx[wid] = emax; }
        __syncthreads();
        if (wid == 0) {
            unsigned a = (lane < 8) ? smn[lane] : 0xFFFFFFFFu;
            unsigned c = (lane < 8) ? smx[lane] : 0u;
            a = __reduce_min_sync(0xFFFFFFFFu, a);
            c = __reduce_max_sync(0xFFFFFFFFu, c);
            if (lane == 0) {
                float xmin = dec_f32(a), xmax = dec_f32(c);
                g_xminF = xmin; g_xmaxF = xmax;
                float range = xmax - xmin;
                g_bsF = (float)NB / range;
                g_binwF = range / (float)NB;
            }
        }
    }
    gbar(&g_bars[0], K2G);

    float xmin = g_xminF, xmax = g_xmaxF, bs = g_bsF;

    // phase 1: candidates + boundaries
    if (gid < NCAND) {
        float s, z, nm, nx;
        cand_params(gid, xmin, xmax, s, z, nm, nx);
        g_scale[gid] = s; g_zp[gid] = z; g_cmin[gid] = nm; g_cmax[gid] = nx;
    }
    if (gid < NBND) {
        int c = gid / 15, k = gid % 15 + 1;
        float s, z, nm, nx;
        cand_params(c, xmin, xmax, s, z, nm, nx);
        double bd = (double)s * ((double)k - (double)z - 0.5);
        float bf = (float)bd;
        int j = binof(bf, xmin, bs);
        g_bndval[gid] = bf;
        g_bndbin[gid] = j;
        atomicAdd(&g_bndcnt[j], 1u);
        atomicOr(&g_bitmap[j >> 5], 1u << (j & 31));
    }
    gbar(&g_bars[1], K2G);

    // phase 2a: per-partition scan (1024 bins / block, 4 per thread)
    int base = b * 1024;
    uint4 cc = *(const uint4*)&g_bndcnt[base + t * 4];
    unsigned ts = cc.x + cc.y + cc.z + cc.w;
    __shared__ unsigned sh[256];
    sh[t] = ts;
    __syncthreads();
    for (int off = 1; off < 256; off <<= 1) {
        unsigned v = (t >= off) ? sh[t - off] : 0u;
        __syncthreads();
        sh[t] += v;
        __syncthreads();
    }
    unsigned excl = sh[t] - ts;
    unsigned o0 = excl, o1 = o0 + cc.x, o2 = o1 + cc.y, o3 = o2 + cc.z;
    if (t == 255) g_psum2[b] = sh[255];
    gbar(&g_bars[2], K2G);

    // phase 2b: block offset + write meta/cursors
    __shared__ unsigned shoff;
    if (t == 0) {
        unsigned o = 0;
        for (int q = 0; q < b; ++q) o += __ldcg(&g_psum2[q]);
        shoff = o;
    }
    __syncthreads();
    unsigned off = shoff;
    g_bndmeta[base + t * 4 + 0] = ((o0 + off) << 16) | cc.x;
    g_bndmeta[base + t * 4 + 1] = ((o1 + off) << 16) | cc.y;
    g_bndmeta[base + t * 4 + 2] = ((o2 + off) << 16) | cc.z;
    g_bndmeta[base + t * 4 + 3] = ((o3 + off) << 16) | cc.w;
    g_bndcur[base + t * 4 + 0] = o0 + off;
    g_bndcur[base + t * 4 + 1] = o1 + off;
    g_bndcur[base + t * 4 + 2] = o2 + off;
    g_bndcur[base + t * 4 + 3] = o3 + off;
    gbar(&g_bars[3], K2G);

    // phase 3: CSR scatter
    if (gid < NBND) {
        int j = g_bndbin[gid];
        unsigned pos = atomicAdd(&g_bndcur[j], 1u);
        g_list[pos] = make_uint2(__float_as_uint(g_bndval[gid]), (unsigned)gid);
    }
}

// ================= k3: heavy pass (acc atomics + boundary partials) =========
__device__ __forceinline__ void main_one(float v, float xmin, float bs, float binw,
                                         const unsigned* __restrict__ bm) {
    int j = binof(v, xmin, bs);
    float offs = fmaxf(v - binlo(j, xmin, binw), 0.0f);
    unsigned long long pk = (1ULL << 48) | (unsigned long long)(offs * FXS);
    atomicAdd(&g_acc[j], pk);
    if ((bm[j >> 5] >> (j & 31)) & 1u) {
        unsigned m = __ldg(&g_bndmeta[j]);
        unsigned b0 = m >> 16, cnt = m & 0xFFFFu;
        for (unsigned q = b0; q < b0 + cnt; ++q) {
            uint2 e = __ldg(&g_list[q]);
            if (v < __uint_as_float(e.x))
                atomicAdd(&g_part[e.y], pk);
        }
    }
}

__global__ void __launch_bounds__(TPB) k3_main(const float* __restrict__ x, int n) {
    __shared__ unsigned bm[NB / 32];
    for (int i = threadIdx.x; i < NB / 32; i += TPB) bm[i] = g_bitmap[i];
    __syncthreads();
    float xmin = g_xminF, bs = g_bsF, binw = g_binwF;

    int tid = blockIdx.x * TPB + threadIdx.x;
    int stride = GRID3 * TPB;
    int n4 = n >> 2;
    const float4* x4 = (const float4*)x;
    for (int p = tid; p < n4; p += stride) {
        float4 v = __ldg(x4 + p);
        main_one(v.x, xmin, bs, binw, bm);
        main_one(v.y, xmin, bs, binw, bm);
        main_one(v.z, xmin, bs, binw, bm);
        main_one(v.w, xmin, bs, binw, bm);
    }
    int r = n & 3;
    if (tid < r) main_one(x[n - r + tid], xmin, bs, binw, bm);
}

// ================= k4: scan + eval + argmin + scratch re-zero ===============
__global__ void __launch_bounds__(K4T, 1) k4_final(float* __restrict__ out, int n) {
    int t = threadIdx.x, b = blockIdx.x;
    int lane = t & 31, wid = t >> 5;          // 16 warps
    float xmin = g_xminF, binw = g_binwF;

    __shared__ unsigned swc[16];
    __shared__ double   swx[16];
    __shared__ unsigned sbc;
    __shared__ double   sbx;
    __shared__ unsigned shc[K4T];   // argmin (block 0)
    __shared__ double   shd[K4T];

    // ---- decode 2 bins/thread; re-zero g_acc for the next replay ----
    int j0 = (b * K4T + t) * 2;
    ulonglong2 aa = *(const ulonglong2*)&g_acc[j0];
    *(ulonglong2*)&g_acc[j0] = make_ulonglong2(0ULL, 0ULL);
    unsigned c0 = (unsigned)(aa.x >> 48);
    unsigned c1 = (unsigned)(aa.y >> 48);
    double dx0 = (double)c0 * (double)binlo(j0,     xmin, binw) + (double)(aa.x & PMASK) * FXSI;
    double dx1 = (double)c1 * (double)binlo(j0 + 1, xmin, binw) + (double)(aa.y & PMASK) * FXSI;
    unsigned tc = c0 + c1;
    double   tx = dx0 + dx1;

    // re-zero per-bin boundary scratch (last consumers were k2/k3)
    g_bndcnt[j0] = 0u;
    g_bndcnt[j0 + 1] = 0u;
    int gg = b * K4T + t;
    if (gg < NB / 32) g_bitmap[gg] = 0u;

    // ---- warp inclusive shuffle scan (fixed order) ----
    unsigned ic = tc; double ix = tx;
    #pragma unroll
    for (int off = 1; off < 32; off <<= 1) {
        unsigned uc = __shfl_up_sync(0xFFFFFFFFu, ic, off);
        double   ux = __shfl_up_sync(0xFFFFFFFFu, ix, off);
        if (lane >= off) { ic += uc; ix += ux; }
    }
    if (lane == 31) { swc[wid] = ic; swx[wid] = ix; }
    __syncthreads();
    // ---- warp 0 scans the 16 warp totals ----
    if (wid == 0) {
        unsigned wc = (lane < 16) ? swc[lane] : 0u;
        double   wx = (lane < 16) ? swx[lane] : 0.0;
        unsigned jc = wc; double jx = wx;
        #pragma unroll
        for (int off = 1; off < 32; off <<= 1) {
            unsigned uc = __shfl_up_sync(0xFFFFFFFFu, jc, off);
            double   ux = __shfl_up_sync(0xFFFFFFFFu, jx, off);
            if (lane >= off) { jc += uc; jx += ux; }
        }
        if (lane < 16) { swc[lane] = jc - wc; swx[lane] = jx - wx; }
        if (lane == 15) { g_ptotc[b] = jc; g_ptotx[b] = jx; }
    }
    __syncthreads();
    unsigned exlc = (ic - tc) + swc[wid];   // block-relative exclusive prefix
    double   exlx = (ix - tx) + swx[wid];
    gbar(&g_bars[4], K4G);

    // ---- cross-block exclusive offsets: warp 0, 4 totals/lane ----
    if (wid == 0) {
        unsigned e0c = __ldcg(&g_ptotc[4 * lane]);
        unsigned e1c = __ldcg(&g_ptotc[4 * lane + 1]);
        unsigned e2c = __ldcg(&g_ptotc[4 * lane + 2]);
        unsigned e3c = __ldcg(&g_ptotc[4 * lane + 3]);
        double   e0x = __ldcg(&g_ptotx[4 * lane]);
        double   e1x = __ldcg(&g_ptotx[4 * lane + 1]);
        double   e2x = __ldcg(&g_ptotx[4 * lane + 2]);
        double   e3x = __ldcg(&g_ptotx[4 * lane + 3]);
        unsigned qc = e0c + e1c + e2c + e3c;
        double   qx = e0x + e1x + e2x + e3x;
        unsigned jc = qc; double jx = qx;
        #pragma unroll
        for (int off = 1; off < 32; off <<= 1) {
            unsigned uc = __shfl_up_sync(0xFFFFFFFFu, jc, off);
            double   ux = __shfl_up_sync(0xFFFFFFFFu, jx, off);
            if (lane >= off) { jc += uc; jx += ux; }
        }
        unsigned gexc = jc - qc; double gexx = jx - qx;   // excl before group 4*lane
        if (b == 0 && lane == 31) g_totsx = jx;            // global total
        int gsel = b >> 2, rsel = b & 3;
        unsigned bc = __shfl_sync(0xFFFFFFFFu, gexc, gsel);
        double   bx = __shfl_sync(0xFFFFFFFFu, gexx, gsel);
        unsigned a0c = __shfl_sync(0xFFFFFFFFu, e0c, gsel);
        unsigned a1c = __shfl_sync(0xFFFFFFFFu, e1c, gsel);
        unsigned a2c = __shfl_sync(0xFFFFFFFFu, e2c, gsel);
        double   a0x = __shfl_sync(0xFFFFFFFFu, e0x, gsel);
        double   a1x = __shfl_sync(0xFFFFFFFFu, e1x, gsel);
        double   a2x = __shfl_sync(0xFFFFFFFFu, e2x, gsel);
        if (rsel > 0) { bc += a0c; bx += a0x; }
        if (rsel > 1) { bc += a1c; bx += a1x; }
        if (rsel > 2) { bc += a2c; bx += a2x; }
        if (lane == 0) { sbc = bc; sbx = bx; }
    }
    __syncthreads();
    unsigned basec = sbc + exlc;
    double   basex = sbx + exlx;
    g_pwcnt[j0]     = basec;
    g_pwsx[j0]      = basex;
    g_pwcnt[j0 + 1] = basec + c0;
    g_pwsx[j0 + 1]  = basex + dx0;
    gbar(&g_bars[5], K4G);

    // ---- eval: one warp per candidate (128*16 = 2048 warps >= 1600) ----
    int gw = b * 16 + wid;
    if (gw < NCAND) {
        int cand = gw;
        float s = g_scale[cand], z = g_zp[cand];
        double dcnt = 0.0, dsx = 0.0;
        if (lane >= 1 && lane <= 15) {
            int id = cand * 15 + (lane - 1);
            int jj = g_bndbin[id];
            unsigned long long pp = __ldcg(&g_part[id]);
            g_part[id] = 0ULL;                       // re-zero for next replay
            unsigned pcnt = (unsigned)(pp >> 48);
            double poff = (double)(pp & PMASK) * FXSI;
            dcnt = (double)__ldcg(&g_pwcnt[jj]) + (double)pcnt;
            dsx  = __ldcg(&g_pwsx[jj])
                 + (double)pcnt * (double)binlo(jj, xmin, binw) + poff;
        } else if (lane == 16) {
            dcnt = (double)n;
            dsx  = __ldcg(&g_totsx);
        }
        __syncwarp();
        double ncnt = __shfl_down_sync(0xFFFFFFFFu, dcnt, 1);
        double nsx  = __shfl_down_sync(0xFFFFFFFFu, dsx, 1);
        double term = 0.0;
        if (lane < 16) {
            float v = ((float)lane - z) * s;
            double vd = (double)v;
            term = vd * vd * (ncnt - dcnt) - 2.0 * vd * (nsx - dsx);
        }
        #pragma unroll
        for (int off = 16; off > 0; off >>= 1)
            term += __shfl_xor_sync(0xFFFFFFFFu, term, off);
        if (lane == 0) g_scores[cand] = term;
    }
    gbar(&g_bars[6], K4G);

    // ---- argmin: block 0 ----
    if (b == 0) {
        double bsd = 1e300;
        int bi = NCAND;
        for (int c = t; c < NCAND; c += K4T) {
            double sv = __ldcg(&g_scores[c]);
            if (sv < bsd) { bsd = sv; bi = c; }
        }
        shd[t] = bsd;
        shc[t] = (unsigned)bi;
        __syncthreads();
        for (int off = K4T / 2; off > 0; off >>= 1) {
            if (t < off) {
                double so = shd[t + off];
                int    io = (int)shc[t + off];
                if (so < shd[t] || (so == shd[t] && io < (int)shc[t])) {
                    shd[t] = so; shc[t] = (unsigned)io;
                }
            }
            __syncthreads();
        }
        if (t == 0) {
            int idx = (int)shc[0];
            out[0] = g_cmin[idx];
            out[1] = g_cmax[idx];
        }
    }
}

// ---------------- launch ----------------
extern "C" void kernel_launch(void* const* d_in, const int* in_sizes, int n_in,
                              void* d_out, int out_size) {
    const float* x = (const float*)d_in[0];
    float* out = (float*)d_out;
    int n = in_sizes[0];

    k1_minmax<<<GRID1, TPB>>>(x, n);
    k2_bnd<<<K2G, 256>>>();
    k3_main<<<GRID3, TPB>>>(x, n);
    k4_final<<<K4G, K4T>>>(out, n);
}

// round 16
// speedup vs baseline: 1.0865x; 1.0865x over previous
#include <cuda_runtime.h>
#include <cstdint>

// ---------------- constants ----------------
#define NCAND   1600
#define NBND    (NCAND * 15)        // 24000
#define NB      131072              // fine value bins
#define TPB     256
#define GRID1   592                 // k1 blocks
#define K2G     128                 // k2 blocks (resident -> grid barrier safe)
#define GRID3   888                 // k3 blocks (6/SM)
#define K4G     128                 // k4 blocks (resident)
#define K4T     512                 // k4 threads (2 bins/thread)
#define EPS_F32 1.1920928955078125e-07f
#define FXS     1099511627776.0f    // 2^40
#define FXSI    (1.0 / 1099511627776.0)
#define PMASK   0x0000FFFFFFFFFFFFULL

// ---------------- device state (zero-initialized at module load; every ------
// ---------------- consumer re-zeroes what it finishes with, so replays ------
// ---------------- always start from zeroed scratch) --------------------------
__device__ unsigned g_bminenc[GRID1], g_bmaxenc[GRID1];
__device__ float    g_xminF, g_xmaxF, g_bsF, g_binwF;
__device__ float    g_scale[NCAND], g_zp[NCAND], g_cmin[NCAND], g_cmax[NCAND];
__device__ float    g_bndval[NBND];
__device__ int      g_bndbin[NBND];
__device__ unsigned g_bndcnt[NB];
__device__ unsigned g_bndmeta[NB];      // (csr_off << 16) | cnt
__device__ unsigned g_bndcur[NB];
__device__ uint2    g_list[NBND];       // {valbits, id}
__device__ unsigned g_bitmap[NB / 32];
__device__ __align__(16) unsigned long long g_acc[NB];
__device__ unsigned long long g_part[NBND];
__device__ unsigned g_pwcnt[NB];
__device__ double   g_pwsx[NB];
__device__ unsigned g_psum2[K2G];
__device__ unsigned g_ptotc[K4G];
__device__ double   g_ptotx[K4G];
__device__ double   g_totsx;
__device__ double   g_scores[NCAND];
__device__ unsigned g_bars[8];

// ---------------- helpers ----------------
__device__ __forceinline__ unsigned enc_f32(float f) {
    unsigned u = __float_as_uint(f);
    return (u & 0x80000000u) ? ~u : (u | 0x80000000u);
}
__device__ __forceinline__ float dec_f32(unsigned e) {
    unsigned u = (e & 0x80000000u) ? (e ^ 0x80000000u) : ~e;
    return __uint_as_float(u);
}
__device__ __forceinline__ int binof(float v, float xmin, float bs) {
    int j = (int)((v - xmin) * bs);
    j = j < 0 ? 0 : j;
    return j < NB ? j : (NB - 1);
}
__device__ __forceinline__ float binlo(int j, float xmin, float binw) {
    return __fmaf_rn((float)j, binw, xmin);
}
// fast software grid barrier (CG grid.sync pattern):
// syncthreads (block-scope fence) + one release-atomic arrive + acquire poll.
// No per-thread MEMBAR.GL, no CCTL.IVALL L1 flush. Requires all blocks resident.
// All post-barrier cross-block reads must be __ldcg or first-touch (audited).
__device__ __forceinline__ void gbar(unsigned* ctr, unsigned target) {
    __syncthreads();
    if (threadIdx.x == 0) {
        unsigned old;
        asm volatile("atom.release.gpu.global.add.u32 %0, [%1], %2;"
                     : "=r"(old) : "l"(ctr), "r"(1u) : "memory");
        unsigned v;
        do {
            asm volatile("ld.acquire.gpu.global.u32 %0, [%1];"
                         : "=r"(v) : "l"(ctr) : "memory");
        } while (v < target);
    }
    __syncthreads();
}
__device__ __forceinline__ void cand_params(int c, float x_min, float x_max,
                                            float& scale, float& zp,
                                            float& nmin, float& nmax) {
    float xrange = x_max - x_min;
    int i = c / 16 + 1;
    int j = c % 16;
    float fi = (float)i, zj = (float)j;
    float tmp_max   = __fmul_rn(__fdiv_rn(xrange, 100.0f), fi);
    float tmp_delta = __fdiv_rn(tmp_max, 15.0f);
    float zd = __fmul_rn(zj, tmp_delta);
    nmin = fmaxf(-zd, x_min);
    nmax = fminf(__fsub_rn(tmp_max, zd), x_max);
    float min_neg = fminf(nmin, 0.0f);
    float max_pos = fmaxf(nmax, 0.0f);
    scale = fmaxf(__fdiv_rn(__fsub_rn(max_pos, min_neg), 15.0f), EPS_F32);
    zp = fminf(fmaxf(0.0f - rintf(__fdiv_rn(min_neg, scale)), 0.0f), 15.0f);
}

// ================= k1: global min/max (+ bar reset only) ====================
__global__ void __launch_bounds__(TPB) k1_minmax(const float* __restrict__ x, int n) {
    int tid = blockIdx.x * TPB + threadIdx.x;
    int stride = GRID1 * TPB;
    if (tid < 8) g_bars[tid] = 0u;

    float lmin = 3.4e38f, lmax = -3.4e38f;
    int n4 = n >> 2;
    const float4* x4 = (const float4*)x;
    for (int p = tid; p < n4; p += stride) {
        float4 v = __ldg(x4 + p);
        lmin = fminf(lmin, fminf(fminf(v.x, v.y), fminf(v.z, v.w)));
        lmax = fmaxf(lmax, fmaxf(fmaxf(v.x, v.y), fmaxf(v.z, v.w)));
    }
    int r = n & 3;
    if (tid < r) {
        float v = x[n - r + tid];
        lmin = fminf(lmin, v);
        lmax = fmaxf(lmax, v);
    }
    unsigned emin = __reduce_min_sync(0xFFFFFFFFu, enc_f32(lmin));
    unsigned emax = __reduce_max_sync(0xFFFFFFFFu, enc_f32(lmax));
    __shared__ unsigned smn[TPB / 32], smx[TPB / 32];
    int wid = threadIdx.x >> 5, lane = threadIdx.x & 31;
    if (lane == 0) { smn[wid] = emin; smx[wid] = emax; }
    __syncthreads();
    if (wid == 0) {
        unsigned a = (lane < TPB / 32) ? smn[lane] : 0xFFFFFFFFu;
        unsigned b = (lane < TPB / 32) ? smx[lane] : 0u;
        a = __reduce_min_sync(0xFFFFFFFFu, a);
        b = __reduce_max_sync(0xFFFFFFFFu, b);
        if (lane == 0) { g_bminenc[blockIdx.x] = a; g_bmaxenc[blockIdx.x] = b; }
    }
}

// ================= k2: minmax-reduce + candidates + boundary CSR ============
__global__ void __launch_bounds__(256) k2_bnd() {
    int t = threadIdx.x, b = blockIdx.x;
    int gid = b * 256 + t;
    int wid = t >> 5, lane = t & 31;

    // phase 0: EVERY block redundantly reduces the 592 minmax partials
    // (u32 min/max is order-invariant -> bit-identical across blocks; no barrier)
    __shared__ unsigned sxmin, sxmax;
    {
        unsigned emin = 0xFFFFFFFFu, emax = 0u;
        for (int i = t; i < GRID1; i += 256) {
            emin = min(emin, __ldcg(&g_bminenc[i]));
            emax = max(emax, __ldcg(&g_bmaxenc[i]));
        }
        emin = __reduce_min_sync(0xFFFFFFFFu, emin);
        emax = __reduce_max_sync(0xFFFFFFFFu, emax);
        __shared__ unsigned smn[8], smx[8];
        if (lane == 0) { smn[wid] = emin; smx[wid] = emax; }
        __syncthreads();
        if (wid == 0) {
            unsigned a = (lane < 8) ? smn[lane] : 0xFFFFFFFFu;
            unsigned c = (lane < 8) ? smx[lane] : 0u;
            a = __reduce_min_sync(0xFFFFFFFFu, a);
            c = __reduce_max_sync(0xFFFFFFFFu, c);
            if (lane == 0) {
                sxmin = a; sxmax = c;
                if (b == 0) {
                    float xmn = dec_f32(a), xmx = dec_f32(c);
                    g_xminF = xmn; g_xmaxF = xmx;
                    float range = xmx - xmn;
                    g_bsF = (float)NB / range;
                    g_binwF = range / (float)NB;
                }
            }
        }
        __syncthreads();
    }
    float xmin = dec_f32(sxmin), xmax = dec_f32(sxmax);
    float bs = (float)NB / (xmax - xmin);   // same expression as g_bsF -> bit-identical

    // phase 1: candidates + boundaries
    if (gid < NCAND) {
        float s, z, nm, nx;
        cand_params(gid, xmin, xmax, s, z, nm, nx);
        g_scale[gid] = s; g_zp[gid] = z; g_cmin[gid] = nm; g_cmax[gid] = nx;
    }
    if (gid < NBND) {
        int c = gid / 15, k = gid % 15 + 1;
        float s, z, nm, nx;
        cand_params(c, xmin, xmax, s, z, nm, nx);
        double bd = (double)s * ((double)k - (double)z - 0.5);
        float bf = (float)bd;
        int j = binof(bf, xmin, bs);
        g_bndval[gid] = bf;
        g_bndbin[gid] = j;
        atomicAdd(&g_bndcnt[j], 1u);
        atomicOr(&g_bitmap[j >> 5], 1u << (j & 31));
    }
    gbar(&g_bars[1], K2G);

    // phase 2a: per-partition scan (1024 bins / block, 4 per thread)
    int base = b * 1024;
    uint4 cc = *(const uint4*)&g_bndcnt[base + t * 4];
    unsigned ts = cc.x + cc.y + cc.z + cc.w;
    __shared__ unsigned sh[256];
    sh[t] = ts;
    __syncthreads();
    for (int off = 1; off < 256; off <<= 1) {
        unsigned v = (t >= off) ? sh[t - off] : 0u;
        __syncthreads();
        sh[t] += v;
        __syncthreads();
    }
    unsigned excl = sh[t] - ts;
    unsigned o0 = excl, o1 = o0 + cc.x, o2 = o1 + cc.y, o3 = o2 + cc.z;
    if (t == 255) g_psum2[b] = sh[255];
    gbar(&g_bars[2], K2G);

    // phase 2b: block offset + write meta/cursors
    __shared__ unsigned shoff;
    if (t == 0) {
        unsigned o = 0;
        for (int q = 0; q < b; ++q) o += __ldcg(&g_psum2[q]);
        shoff = o;
    }
    __syncthreads();
    unsigned off = shoff;
    g_bndmeta[base + t * 4 + 0] = ((o0 + off) << 16) | cc.x;
    g_bndmeta[base + t * 4 + 1] = ((o1 + off) << 16) | cc.y;
    g_bndmeta[base + t * 4 + 2] = ((o2 + off) << 16) | cc.z;
    g_bndmeta[base + t * 4 + 3] = ((o3 + off) << 16) | cc.w;
    g_bndcur[base + t * 4 + 0] = o0 + off;
    g_bndcur[base + t * 4 + 1] = o1 + off;
    g_bndcur[base + t * 4 + 2] = o2 + off;
    g_bndcur[base + t * 4 + 3] = o3 + off;
    gbar(&g_bars[3], K2G);

    // phase 3: CSR scatter
    if (gid < NBND) {
        int j = g_bndbin[gid];
        unsigned pos = atomicAdd(&g_bndcur[j], 1u);
        g_list[pos] = make_uint2(__float_as_uint(g_bndval[gid]), (unsigned)gid);
    }
}

// ================= k3: heavy pass (acc atomics + boundary partials) =========
__device__ __forceinline__ void main_one(float v, float xmin, float bs, float binw,
                                         const unsigned* __restrict__ bm) {
    int j = binof(v, xmin, bs);
    float offs = fmaxf(v - binlo(j, xmin, binw), 0.0f);
    unsigned long long pk = (1ULL << 48) | (unsigned long long)(offs * FXS);
    atomicAdd(&g_acc[j], pk);
    if ((bm[j >> 5] >> (j & 31)) & 1u) {
        unsigned m = __ldg(&g_bndmeta[j]);
        unsigned b0 = m >> 16, cnt = m & 0xFFFFu;
        for (unsigned q = b0; q < b0 + cnt; ++q) {
            uint2 e = __ldg(&g_list[q]);
            if (v < __uint_as_float(e.x))
                atomicAdd(&g_part[e.y], pk);
        }
    }
}

__global__ void __launch_bounds__(TPB) k3_main(const float* __restrict__ x, int n) {
    __shared__ unsigned bm[NB / 32];
    for (int i = threadIdx.x; i < NB / 32; i += TPB) bm[i] = g_bitmap[i];
    __syncthreads();
    float xmin = g_xminF, bs = g_bsF, binw = g_binwF;

    int tid = blockIdx.x * TPB + threadIdx.x;
    int stride = GRID3 * TPB;
    int n4 = n >> 2;
    const float4* x4 = (const float4*)x;
    for (int p = tid; p < n4; p += stride) {
        float4 v = __ldg(x4 + p);
        main_one(v.x, xmin, bs, binw, bm);
        main_one(v.y, xmin, bs, binw, bm);
        main_one(v.z, xmin, bs, binw, bm);
        main_one(v.w, xmin, bs, binw, bm);
    }
    int r = n & 3;
    if (tid < r) main_one(x[n - r + tid], xmin, bs, binw, bm);
}

// ================= k4: scan + eval + argmin + scratch re-zero ===============
__global__ void __launch_bounds__(K4T, 1) k4_final(float* __restrict__ out, int n) {
    int t = threadIdx.x, b = blockIdx.x;
    int lane = t & 31, wid = t >> 5;          // 16 warps
    float xmin = g_xminF, binw = g_binwF;

    __shared__ unsigned swc[16];
    __shared__ double   swx[16];
    __shared__ unsigned sbc;
    __shared__ double   sbx;
    __shared__ unsigned shc[K4T];   // argmin (block 0)
    __shared__ double   shd[K4T];

    // ---- decode 2 bins/thread; re-zero g_acc for the next replay ----
    int j0 = (b * K4T + t) * 2;
    ulonglong2 aa = *(const ulonglong2*)&g_acc[j0];
    *(ulonglong2*)&g_acc[j0] = make_ulonglong2(0ULL, 0ULL);
    unsigned c0 = (unsigned)(aa.x >> 48);
    unsigned c1 = (unsigned)(aa.y >> 48);
    double dx0 = (double)c0 * (double)binlo(j0,     xmin, binw) + (double)(aa.x & PMASK) * FXSI;
    double dx1 = (double)c1 * (double)binlo(j0 + 1, xmin, binw) + (double)(aa.y & PMASK) * FXSI;
    unsigned tc = c0 + c1;
    double   tx = dx0 + dx1;

    // re-zero per-bin boundary scratch (last consumers were k2/k3)
    g_bndcnt[j0] = 0u;
    g_bndcnt[j0 + 1] = 0u;
    int gg = b * K4T + t;
    if (gg < NB / 32) g_bitmap[gg] = 0u;

    // ---- warp inclusive shuffle scan (fixed order) ----
    unsigned ic = tc; double ix = tx;
    #pragma unroll
    for (int off = 1; off < 32; off <<= 1) {
        unsigned uc = __shfl_up_sync(0xFFFFFFFFu, ic, off);
        double   ux = __shfl_up_sync(0xFFFFFFFFu, ix, off);
        if (lane >= off) { ic += uc; ix += ux; }
    }
    if (lane == 31) { swc[wid] = ic; swx[wid] = ix; }
    __syncthreads();
    // ---- warp 0 scans the 16 warp totals ----
    if (wid == 0) {
        unsigned wc = (lane < 16) ? swc[lane] : 0u;
        double   wx = (lane < 16) ? swx[lane] : 0.0;
        unsigned jc = wc; double jx = wx;
        #pragma unroll
        for (int off = 1; off < 32; off <<= 1) {
            unsigned uc = __shfl_up_sync(0xFFFFFFFFu, jc, off);
            double   ux = __shfl_up_sync(0xFFFFFFFFu, jx, off);
            if (lane >= off) { jc += uc; jx += ux; }
        }
        if (lane < 16) { swc[lane] = jc - wc; swx[lane] = jx - wx; }
        if (lane == 15) { g_ptotc[b] = jc; g_ptotx[b] = jx; }
    }
    __syncthreads();
    unsigned exlc = (ic - tc) + swc[wid];   // block-relative exclusive prefix
    double   exlx = (ix - tx) + swx[wid];
    gbar(&g_bars[4], K4G);

    // ---- cross-block exclusive offsets: warp 0, 4 totals/lane ----
    if (wid == 0) {
        unsigned e0c = __ldcg(&g_ptotc[4 * lane]);
        unsigned e1c = __ldcg(&g_ptotc[4 * lane + 1]);
        unsigned e2c = __ldcg(&g_ptotc[4 * lane + 2]);
        unsigned e3c = __ldcg(&g_ptotc[4 * lane + 3]);
        double   e0x = __ldcg(&g_ptotx[4 * lane]);
        double   e1x = __ldcg(&g_ptotx[4 * lane + 1]);
        double   e2x = __ldcg(&g_ptotx[4 * lane + 2]);
        double   e3x = __ldcg(&g_ptotx[4 * lane + 3]);
        unsigned qc = e0c + e1c + e2c + e3c;
        double   qx = e0x + e1x + e2x + e3x;
        unsigned jc = qc; double jx = qx;
        #pragma unroll
        for (int off = 1; off < 32; off <<= 1) {
            unsigned uc = __shfl_up_sync(0xFFFFFFFFu, jc, off);
            double   ux = __shfl_up_sync(0xFFFFFFFFu, jx, off);
            if (lane >= off) { jc += uc; jx += ux; }
        }
        unsigned gexc = jc - qc; double gexx = jx - qx;   // excl before group 4*lane
        if (b == 0 && lane == 31) g_totsx = jx;            // global total
        int gsel = b >> 2, rsel = b & 3;
        unsigned bc = __shfl_sync(0xFFFFFFFFu, gexc, gsel);
        double   bx = __shfl_sync(0xFFFFFFFFu, gexx, gsel);
        unsigned a0c = __shfl_sync(0xFFFFFFFFu, e0c, gsel);
        unsigned a1c = __shfl_sync(0xFFFFFFFFu, e1c, gsel);
        unsigned a2c = __shfl_sync(0xFFFFFFFFu, e2c, gsel);
        double   a0x = __shfl_sync(0xFFFFFFFFu, e0x, gsel);
        double   a1x = __shfl_sync(0xFFFFFFFFu, e1x, gsel);
        double   a2x = __shfl_sync(0xFFFFFFFFu, e2x, gsel);
        if (rsel > 0) { bc += a0c; bx += a0x; }
        if (rsel > 1) { bc += a1c; bx += a1x; }
        if (rsel > 2) { bc += a2c; bx += a2x; }
        if (lane == 0) { sbc = bc; sbx = bx; }
    }
    __syncthreads();
    unsigned basec = sbc + exlc;
    double   basex = sbx + exlx;
    g_pwcnt[j0]     = basec;
    g_pwsx[j0]      = basex;
    g_pwcnt[j0 + 1] = basec + c0;
    g_pwsx[j0 + 1]  = basex + dx0;
    gbar(&g_bars[5], K4G);

    // ---- eval: one warp per candidate (128*16 = 2048 warps >= 1600) ----
    int gw = b * 16 + wid;
    if (gw < NCAND) {
        int cand = gw;
        float s = g_scale[cand], z = g_zp[cand];
        double dcnt = 0.0, dsx = 0.0;
        if (lane >= 1 && lane <= 15) {
            int id = cand * 15 + (lane - 1);
            int jj = g_bndbin[id];
            unsigned long long pp = __ldcg(&g_part[id]);
            g_part[id] = 0ULL;                       // re-zero for next replay
            unsigned pcnt = (unsigned)(pp >> 48);
            double poff = (double)(pp & PMASK) * FXSI;
            dcnt = (double)__ldcg(&g_pwcnt[jj]) + (double)pcnt;
            dsx  = __ldcg(&g_pwsx[jj])
                 + (double)pcnt * (double)binlo(jj, xmin, binw) + poff;
        } else if (lane == 16) {
            dcnt = (double)n;
            dsx  = __ldcg(&g_totsx);
        }
        __syncwarp();
        double ncnt = __shfl_down_sync(0xFFFFFFFFu, dcnt, 1);
        double nsx  = __shfl_down_sync(0xFFFFFFFFu, dsx, 1);
        double term = 0.0;
        if (lane < 16) {
            float v = ((float)lane - z) * s;
            double vd = (double)v;
            term = vd * vd * (ncnt - dcnt) - 2.0 * vd * (nsx - dsx);
        }
        #pragma unroll
        for (int off = 16; off > 0; off >>= 1)
            term += __shfl_xor_sync(0xFFFFFFFFu, term, off);
        if (lane == 0) g_scores[cand] = term;
    }
    gbar(&g_bars[6], K4G);

    // ---- argmin: block 0 ----
    if (b == 0) {
        double bsd = 1e300;
        int bi = NCAND;
        for (int c = t; c < NCAND; c += K4T) {
            double sv = __ldcg(&g_scores[c]);
            if (sv < bsd) { bsd = sv; bi = c; }
        }
        shd[t] = bsd;
        shc[t] = (unsigned)bi;
        __syncthreads();
        for (int off = K4T / 2; off > 0; off >>= 1) {
            if (t < off) {
                double so = shd[t + off];
                int    io = (int)shc[t + off];
                if (so < shd[t] || (so == shd[t] && io < (int)shc[t])) {
                    shd[t] = so; shc[t] = (unsigned)io;
                }
            }
            __syncthreads();
        }
        if (t == 0) {
            int idx = (int)shc[0];
            out[0] = g_cmin[idx];
            out[1] = g_cmax[idx];
        }
    }
}

// ---------------- launch ----------------
extern "C" void kernel_launch(void* const* d_in, const int* in_sizes, int n_in,
                              void* d_out, int out_size) {
    const float* x = (const float*)d_in[0];
    float* out = (float*)d_out;
    int n = in_sizes[0];

    k1_minmax<<<GRID1, TPB>>>(x, n);
    k2_bnd<<<K2G, 256>>>();
    k3_main<<<GRID3, TPB>>>(x, n);
    k4_final<<<K4G, K4T>>>(out, n);
}